// round 14
// baseline (speedup 1.0000x reference)
#include <cuda_runtime.h>
#include <cuda_bf16.h>

// ROI mean-pool, v14: v11 single-buffer shape with 3-way segment split.
//   fused load+col-scan: 240 threads (80 cols x 3 segments, 27/27/26 rows)
//   row scan:            240 threads (80 rows x 3 x-parts,  27/27/26 cols)
//   box phase:           O(1) doubly-stitched corners
//
// fmap: [64,256,80,80] f32   boxes: [64,100,4]   out: [64,100,256]
//
// M[80][81] (odd stride -> conflict-free everywhere).
// After col scan: A[r][x] = sum of f over rows of r's segment up to r.
//   True col prefix C[y] = A[y-1] + [y-1>=27] A[26] + [y-1>=54] A[53].
// After row scan (within x-parts 0-26|27-53|54-79):
//   P(r,x) = R[r][xi] + [xi>=27] R[r][26] + [xi>=54] R[r][53]  (xi=x-1)
// g(y,x) = P(r0,x) + [r0>=27] P(26,x) + [r0>=54] P(53,x),  r0=y-1.

#define Bn   64
#define Cn   256
#define Hn   80
#define Wn   80
#define Nn   100
#define SSTR 81

__device__ __forceinline__ float Qf(const float* __restrict__ M, int r, int xi)
{
    const float* row = M + r * SSTR;
    float v = row[xi];
    if (xi >= 27) v += row[26];
    if (xi >= 54) v += row[53];
    return v;
}

__device__ __forceinline__ float gfun(const float* __restrict__ M, int y, int x)
{
    if (y == 0 || x == 0) return 0.0f;
    const int r0 = y - 1;
    const int xi = x - 1;
    float v = Qf(M, r0, xi);
    if (r0 >= 27) v += Qf(M, 26, xi);
    if (r0 >= 54) v += Qf(M, 53, xi);
    return v;
}

__global__ __launch_bounds__(256)
void roi_pool_v14_kernel(const float* __restrict__ fmap,
                         const float* __restrict__ boxes,
                         float* __restrict__ out)
{
    __shared__ float M[Hn * SSTR];       // 25,920 B
    __shared__ int4  BC[Nn];

    const int p   = blockIdx.x;          // plane id = b*Cn + c
    const int b   = p >> 8;
    const int c   = p & 255;
    const int tid = threadIdx.x;

    const float* __restrict__ plane = fmap + (size_t)p * (Hn * Wn);

    // ---- Phase 1: fused load + segmented column scan (240 thr) ----------
    if (tid < 240) {
        const int col  = tid % Wn;
        const int seg  = tid / Wn;       // 0,1,2
        const int rowb = seg * 27;       // 0,27,54 ; rows 27,27,26
        const float* __restrict__ g = plane + rowb * Wn + col;
        float*       __restrict__ d = M     + rowb * SSTR + col;

        float acc = 0.0f;
        #pragma unroll 13
        for (int i = 0; i < 26; ++i) {   // compile-time bound, 13 loads/batch
            acc += g[i * Wn];            // coalesced; independent of carry
            d[i * SSTR] = acc;           // conflict-free STS
        }
        if (seg != 2) {                  // segments 0,1 have a 27th row
            acc += g[26 * Wn];
            d[26 * SSTR] = acc;
        }
    } else {
        // Threads 240..255: box coords (overlapped with the plane load).
        const float* __restrict__ bx = boxes + (size_t)b * (Nn * 4);
        for (int n = tid - 240; n < Nn; n += 16) {
            float4 bb = reinterpret_cast<const float4*>(bx)[n];
            // Match JAX exactly: IEEE div by 640, IEEE mul by 80, trunc, clip.
            int x1 = min(max((int)(__fmul_rn(__fdiv_rn(bb.x, 640.0f), 80.0f)), 0), Wn);
            int y1 = min(max((int)(__fmul_rn(__fdiv_rn(bb.y, 640.0f), 80.0f)), 0), Hn);
            int x2 = min(max((int)(__fmul_rn(__fdiv_rn(bb.z, 640.0f), 80.0f)), 0), Wn);
            int y2 = min(max((int)(__fmul_rn(__fdiv_rn(bb.w, 640.0f), 80.0f)), 0), Hn);
            BC[n] = make_int4(x1, y1, x2, y2);
        }
    }
    __syncthreads();

    // ---- Phase 2: segmented row scan (240 thr: 80 rows x 3 x-parts) ------
    // Lanes = consecutive rows at stride 81 (odd) -> conflict-free.
    if (tid < 240) {
        const int r    = tid % Hn;
        const int part = tid / Hn;       // 0,1,2
        float* d = M + r * SSTR + part * 27;
        float acc = 0.0f;
        #pragma unroll 13
        for (int i = 0; i < 26; ++i) {
            acc += d[i];
            d[i] = acc;
        }
        if (part != 2) {
            acc += d[26];
            d[26] = acc;
        }
    }
    __syncthreads();

    // ---- Phase 3: O(1) box phase (avg ~16, max 36 scalar LDS) ------------
    if (tid < Nn) {
        int4 q = BC[tid];                // x1,y1,x2,y2
        float s = gfun(M, q.w, q.z) - gfun(M, q.y, q.z)
                - gfun(M, q.w, q.x) + gfun(M, q.y, q.x);

        int dy = q.w - q.y;
        int dx = q.z - q.x;
        bool valid = (dy > 0) && (dx > 0);
        int  area  = max(dy * dx, 1);

        out[(size_t)b * (Nn * Cn) + (size_t)tid * Cn + c] =
            valid ? s / (float)area : 0.0f;
    }
}

extern "C" void kernel_launch(void* const* d_in, const int* in_sizes, int n_in,
                              void* d_out, int out_size)
{
    const float* fmap  = (const float*)d_in[0];   // [64,256,80,80]
    const float* boxes = (const float*)d_in[1];   // [64,100,4]
    float*       out   = (float*)d_out;           // [64,100,256]

    (void)in_sizes; (void)n_in; (void)out_size;

    roi_pool_v14_kernel<<<Bn * Cn, 256>>>(fmap, boxes, out);
}

// round 15
// speedup vs baseline: 1.1783x; 1.1783x over previous
#include <cuda_runtime.h>
#include <cuda_bf16.h>

// ROI mean-pool, v15: cross-plane pipelined v11/v14 hybrid.
//   Each CTA: 8 consecutive planes. Next plane staged in REGISTERS (27
//   independent LDGs/thread) issued before the current plane's row scan,
//   so DRAM stays busy during compute. Single smem buffer (27.5 KB).
//   Scan arithmetic = v14 (3 segments, stitched corners), proven correct.
//
// fmap: [64,256,80,80] f32   boxes: [64,100,4]   out: [64,100,256]
//
// M[80][81] (odd stride -> conflict-free everywhere).
// col scan (regs->STS): A[r][x] = seg-local col prefix (segs rows 0-26|27-53|54-79)
// row scan (in place):  x-prefix within parts x 0-26|27-53|54-79
// Qf(r,xi) = R[r][xi] + [xi>=27] R[r][26] + [xi>=54] R[r][53]
// g(y,x)   = Qf(r0,xi) + [r0>=27] Qf(26,xi) + [r0>=54] Qf(53,xi), r0=y-1, xi=x-1

#define Bn   64
#define Cn   256
#define Hn   80
#define Wn   80
#define Nn   100
#define SSTR 81
#define KPL  8
#define SEGR 27                      // rows per segment (last has 26)

__device__ __forceinline__ float Qf(const float* __restrict__ M, int r, int xi)
{
    const float* row = M + r * SSTR;
    float v = row[xi];
    if (xi >= 27) v += row[26];
    if (xi >= 54) v += row[53];
    return v;
}

__device__ __forceinline__ float gfun(const float* __restrict__ M, int y, int x)
{
    if (y == 0 || x == 0) return 0.0f;
    const int r0 = y - 1;
    const int xi = x - 1;
    float v = Qf(M, r0, xi);
    if (r0 >= 27) v += Qf(M, 26, xi);
    if (r0 >= 54) v += Qf(M, 53, xi);
    return v;
}

__global__ __launch_bounds__(256)
void roi_pool_v15_kernel(const float* __restrict__ fmap,
                         const float* __restrict__ boxes,
                         float* __restrict__ out)
{
    __shared__ float M[Hn * SSTR];       // 25,920 B
    __shared__ int4  BC[Nn];             // 1,600 B

    const int p0  = blockIdx.x * KPL;    // 8 consecutive planes, same b
    const int b   = p0 >> 8;
    const int c0  = p0 & 255;
    const int tid = threadIdx.x;

    const int col = tid % Wn;            // valid for tid<240
    const int seg = tid / Wn;            // 0,1,2
    const int nrows = (seg == 2) ? 26 : 27;

    const float* __restrict__ gcol =
        fmap + (size_t)p0 * (Hn * Wn) + (seg * SEGR) * Wn + col;

    float v[SEGR];                       // staged next-plane column values

    // ---- Prologue: stage plane 0 | box coords ----------------------------
    if (tid < 240) {
        #pragma unroll
        for (int i = 0; i < SEGR; ++i)
            if (i < nrows) v[i] = gcol[i * Wn];      // independent LDGs
    } else {
        const float* __restrict__ bx = boxes + (size_t)b * (Nn * 4);
        for (int n = tid - 240; n < Nn; n += 16) {
            float4 bb = reinterpret_cast<const float4*>(bx)[n];
            // Match JAX exactly: IEEE div by 640, IEEE mul by 80, trunc, clip.
            int x1 = min(max((int)(__fmul_rn(__fdiv_rn(bb.x, 640.0f), 80.0f)), 0), Wn);
            int y1 = min(max((int)(__fmul_rn(__fdiv_rn(bb.y, 640.0f), 80.0f)), 0), Hn);
            int x2 = min(max((int)(__fmul_rn(__fdiv_rn(bb.z, 640.0f), 80.0f)), 0), Wn);
            int y2 = min(max((int)(__fmul_rn(__fdiv_rn(bb.w, 640.0f), 80.0f)), 0), Hn);
            BC[n] = make_int4(x1, y1, x2, y2);
        }
    }

    #pragma unroll 1
    for (int k = 0; k < KPL; ++k) {
        // ---- Column scan of staged regs -> prefix STS --------------------
        if (tid < 240) {
            float acc = 0.0f;
            float* d = M + (seg * SEGR) * SSTR + col;
            #pragma unroll
            for (int i = 0; i < SEGR; ++i)
                if (i < nrows) {
                    acc += v[i];
                    d[i * SSTR] = acc;   // conflict-free STS
                }
        }
        __syncthreads();                 // prefix (and, at k=0, BC) visible

        // ---- Stage NEXT plane into registers (flies under the compute) ---
        if (k + 1 < KPL && tid < 240) {
            const float* __restrict__ gn = gcol + (size_t)(k + 1) * (Hn * Wn);
            #pragma unroll
            for (int i = 0; i < SEGR; ++i)
                if (i < nrows) v[i] = gn[i * Wn];
        }

        // ---- Row scan in place (240 thr: 80 rows x 3 x-parts) ------------
        if (tid < 240) {
            const int r    = tid % Hn;
            const int part = tid / Hn;
            float* d = M + r * SSTR + part * SEGR;
            float acc = 0.0f;
            #pragma unroll 13
            for (int i = 0; i < 26; ++i) {
                acc += d[i];
                d[i] = acc;
            }
            if (part != 2) {
                acc += d[26];
                d[26] = acc;
            }
        }
        __syncthreads();

        // ---- Box phase: O(1) stitched corners ----------------------------
        if (tid < Nn) {
            int4 q = BC[tid];
            float s = gfun(M, q.w, q.z) - gfun(M, q.y, q.z)
                    - gfun(M, q.w, q.x) + gfun(M, q.y, q.x);
            int dy = q.w - q.y;
            int dx = q.z - q.x;
            bool valid = (dy > 0) && (dx > 0);
            int  area  = max(dy * dx, 1);
            out[(size_t)b * (Nn * Cn) + (size_t)tid * Cn + (c0 + k)] =
                valid ? s / (float)area : 0.0f;
        }
        __syncthreads();                 // M free before next STS
    }
}

extern "C" void kernel_launch(void* const* d_in, const int* in_sizes, int n_in,
                              void* d_out, int out_size)
{
    const float* fmap  = (const float*)d_in[0];   // [64,256,80,80]
    const float* boxes = (const float*)d_in[1];   // [64,100,4]
    float*       out   = (float*)d_out;           // [64,100,256]

    (void)in_sizes; (void)n_in; (void)out_size;

    roi_pool_v15_kernel<<<(Bn * Cn) / KPL, 256>>>(fmap, boxes, out);
}